// round 11
// baseline (speedup 1.0000x reference)
#include <cuda_runtime.h>
#include <cooperative_groups.h>
namespace cg = cooperative_groups;

#define BB 32
#define CC 512
#define HC 128
#define HW 4096
#define NPLANE (BB * CC)
#define GROUP 16                     /* batches per group: 16*512*16KB = 134MB ~ L2 */
#define NGROUP (BB / GROUP)
#define GPLANES (GROUP * CC)
#define EPS_BN 0.001f

// scratch (no device allocations allowed anywhere)
__device__ float g_s[BB * CC];      // pooled means [B, C]
__device__ float g_es[BB * CC];     // e * scale2   [B, C]
__device__ float g_shift[CC];       // shift2       [C]

// ---------------------------------------------------------------------------
// Persistent cooperative kernel: per group of 16 batches,
//   phase R: per-plane means (DRAM reads, fills L2)
//   phase E: excitation MLP (16 blocks)
//   phase S: y = x*es + shift (reads from L2, DRAM writes)
// grid.sync() keeps the DRAM traffic phase-pure (no read/write mixing).
// ---------------------------------------------------------------------------
__global__ void __launch_bounds__(256) se_all(
    const float* __restrict__ x, float* __restrict__ y,
    const float* __restrict__ w1, const float* __restrict__ g1,
    const float* __restrict__ b1, const float* __restrict__ m1,
    const float* __restrict__ v1, const float* __restrict__ w2,
    const float* __restrict__ g2, const float* __restrict__ b2,
    const float* __restrict__ m2, const float* __restrict__ v2) {

    cg::grid_group grid = cg::this_grid();
    const int tid  = threadIdx.x;
    const int wid  = tid >> 5;
    const int lane = tid & 31;
    __shared__ float red[8];
    __shared__ float s_s[CC];
    __shared__ float s_h[HC];

    for (int g = 0; g < NGROUP; g++) {
        const int pbase = g * GPLANES;

        // ---------------- phase R: reduce ----------------
        for (int p = blockIdx.x; p < GPLANES; p += gridDim.x) {
            const int plane = pbase + p;
            const float4* xp = reinterpret_cast<const float4*>(x) +
                               (size_t)plane * (HW / 4) + tid;
            float sum = 0.f;
#pragma unroll
            for (int i = 0; i < 4; i++) {
                float4 v = __ldcg(xp + i * 256);   // allocate in L2 for phase S
                sum += (v.x + v.y) + (v.z + v.w);
            }
#pragma unroll
            for (int o = 16; o > 0; o >>= 1)
                sum += __shfl_down_sync(0xffffffffu, sum, o);
            if (lane == 0) red[wid] = sum;
            __syncthreads();
            if (tid == 0) {
                float s = 0.f;
#pragma unroll
                for (int i = 0; i < 8; i++) s += red[i];
                g_s[plane] = s * (1.0f / HW);
            }
            __syncthreads();                        // red[] reused next iter
        }
        grid.sync();

        // ---------------- phase E: excitation ----------------
        if (blockIdx.x < GROUP) {
            const int b = g * GROUP + blockIdx.x;
            for (int i = tid; i < CC; i += 256) s_s[i] = g_s[b * CC + i];
            __syncthreads();

#pragma unroll 2
            for (int r = 0; r < 16; r++) {
                const int j = wid * 16 + r;
                const float* wr = w1 + j * CC;
                float acc = 0.f;
#pragma unroll
                for (int i = 0; i < CC / 32; i++)
                    acc = fmaf(wr[lane + 32 * i], s_s[lane + 32 * i], acc);
#pragma unroll
                for (int o = 16; o > 0; o >>= 1)
                    acc += __shfl_down_sync(0xffffffffu, acc, o);
                if (lane == 0) {
                    float hv = (acc - m1[j]) * (g1[j] * rsqrtf(v1[j] + EPS_BN)) + b1[j];
                    s_h[j] = fmaxf(hv, 0.f);
                }
            }
            __syncthreads();

#pragma unroll 2
            for (int r = 0; r < 64; r++) {
                const int c = wid * 64 + r;
                const float* wr = w2 + c * HC;
                float acc = 0.f;
#pragma unroll
                for (int i = 0; i < HC / 32; i++)
                    acc = fmaf(wr[lane + 32 * i], s_h[lane + 32 * i], acc);
#pragma unroll
                for (int o = 16; o > 0; o >>= 1)
                    acc += __shfl_down_sync(0xffffffffu, acc, o);
                if (lane == 0) {
                    const float sc2 = g2[c] * rsqrtf(v2[c] + EPS_BN);
                    g_es[b * CC + c] = acc * sc2;
                    if (b == 0) g_shift[c] = fmaf(-m2[c], sc2, b2[c]);
                }
            }
            __syncthreads();
        }
        grid.sync();

        // ---------------- phase S: scale ----------------
        for (int p = blockIdx.x; p < GPLANES; p += gridDim.x) {
            const int plane = pbase + p;
            const float es    = g_es[plane];
            const float shift = g_shift[plane & (CC - 1)];
            const size_t base = (size_t)plane * (HW / 4);
            const float4* xp = reinterpret_cast<const float4*>(x) + base + tid;
            float4*       yp = reinterpret_cast<float4*>(y) + base + tid;

            float4 v[4];
#pragma unroll
            for (int i = 0; i < 4; i++) v[i] = __ldcs(xp + i * 256); // last use
#pragma unroll
            for (int i = 0; i < 4; i++) {
                float4 o;
                o.x = fmaf(v[i].x, es, shift);
                o.y = fmaf(v[i].y, es, shift);
                o.z = fmaf(v[i].z, es, shift);
                o.w = fmaf(v[i].w, es, shift);
                __stcs(yp + i * 256, o);
            }
        }
        grid.sync();                                // keep next group's reads pure
    }
}

// ---------------------------------------------------------------------------
// Fallback kernels (proven R7 path) in case cooperative launch is rejected.
// ---------------------------------------------------------------------------
__global__ void __launch_bounds__(256) se_reduce(const float* __restrict__ x) {
    const int plane = blockIdx.x;
    const float4* xp = reinterpret_cast<const float4*>(x + (size_t)plane * HW) + threadIdx.x;
    float sum = 0.f;
#pragma unroll
    for (int i = 0; i < 4; i++) {
        float4 v = xp[i * 256];
        sum += (v.x + v.y) + (v.z + v.w);
    }
#pragma unroll
    for (int o = 16; o > 0; o >>= 1) sum += __shfl_down_sync(0xffffffffu, sum, o);
    __shared__ float red[8];
    if ((threadIdx.x & 31) == 0) red[threadIdx.x >> 5] = sum;
    __syncthreads();
    if (threadIdx.x == 0) {
        float s = 0.f;
#pragma unroll
        for (int i = 0; i < 8; i++) s += red[i];
        g_s[plane] = s * (1.0f / HW);
    }
}

__global__ void __launch_bounds__(256) se_excite(
    const float* __restrict__ w1, const float* __restrict__ g1,
    const float* __restrict__ b1, const float* __restrict__ m1,
    const float* __restrict__ v1, const float* __restrict__ w2,
    const float* __restrict__ g2, const float* __restrict__ b2,
    const float* __restrict__ m2, const float* __restrict__ v2) {
    __shared__ float s_s[CC];
    __shared__ float s_h[HC];
    const int b = blockIdx.x, wid = threadIdx.x >> 5, lane = threadIdx.x & 31;
    for (int i = threadIdx.x; i < CC; i += 256) s_s[i] = g_s[b * CC + i];
    __syncthreads();
#pragma unroll 2
    for (int r = 0; r < 16; r++) {
        const int j = wid * 16 + r;
        const float* wr = w1 + j * CC;
        float acc = 0.f;
#pragma unroll
        for (int i = 0; i < CC / 32; i++)
            acc = fmaf(wr[lane + 32 * i], s_s[lane + 32 * i], acc);
#pragma unroll
        for (int o = 16; o > 0; o >>= 1) acc += __shfl_down_sync(0xffffffffu, acc, o);
        if (lane == 0) {
            float hv = (acc - m1[j]) * (g1[j] * rsqrtf(v1[j] + EPS_BN)) + b1[j];
            s_h[j] = fmaxf(hv, 0.f);
        }
    }
    __syncthreads();
#pragma unroll 2
    for (int r = 0; r < 64; r++) {
        const int c = wid * 64 + r;
        const float* wr = w2 + c * HC;
        float acc = 0.f;
#pragma unroll
        for (int i = 0; i < HC / 32; i++)
            acc = fmaf(wr[lane + 32 * i], s_h[lane + 32 * i], acc);
#pragma unroll
        for (int o = 16; o > 0; o >>= 1) acc += __shfl_down_sync(0xffffffffu, acc, o);
        if (lane == 0) {
            const float sc2 = g2[c] * rsqrtf(v2[c] + EPS_BN);
            g_es[b * CC + c] = acc * sc2;
            if (b == 0) g_shift[c] = fmaf(-m2[c], sc2, b2[c]);
        }
    }
}

__global__ void __launch_bounds__(256) se_scale(const float* __restrict__ x,
                                                float* __restrict__ y) {
    const int plane0 = NPLANE - 2 - blockIdx.x * 2;
    float es[2], sh[2];
#pragma unroll
    for (int p = 0; p < 2; p++) {
        es[p] = g_es[plane0 + p];
        sh[p] = g_shift[(plane0 + p) & (CC - 1)];
    }
    const size_t base = (size_t)plane0 * (HW / 4);
    const float4* xp = reinterpret_cast<const float4*>(x) + base + threadIdx.x;
    float4*       yp = reinterpret_cast<float4*>(y) + base + threadIdx.x;
    float4 v[8];
#pragma unroll
    for (int i = 0; i < 8; i++) v[i] = __ldcg(xp + i * 256);
#pragma unroll
    for (int i = 0; i < 8; i++) {
        const float e = es[i >> 2], s = sh[i >> 2];
        float4 o;
        o.x = fmaf(v[i].x, e, s); o.y = fmaf(v[i].y, e, s);
        o.z = fmaf(v[i].z, e, s); o.w = fmaf(v[i].w, e, s);
        __stcs(yp + i * 256, o);
    }
}

// ---------------------------------------------------------------------------
extern "C" void kernel_launch(void* const* d_in, const int* in_sizes, int n_in,
                              void* d_out, int out_size) {
    const float* x  = (const float*)d_in[0];
    const float* w1 = (const float*)d_in[1];
    const float* g1 = (const float*)d_in[2];
    const float* b1 = (const float*)d_in[3];
    const float* m1 = (const float*)d_in[4];
    const float* v1 = (const float*)d_in[5];
    const float* w2 = (const float*)d_in[6];
    const float* g2 = (const float*)d_in[7];
    const float* b2 = (const float*)d_in[8];
    const float* m2 = (const float*)d_in[9];
    const float* v2 = (const float*)d_in[10];
    float* y = (float*)d_out;

    // one-time sizing on the first (uncaptured) correctness call
    static int coopGrid = -1;
    if (coopGrid < 0) {
        int dev = 0, sms = 0, perSM = 0;
        cudaGetDevice(&dev);
        cudaDeviceGetAttribute(&sms, cudaDevAttrMultiProcessorCount, dev);
        cudaOccupancyMaxActiveBlocksPerMultiprocessor(&perSM, se_all, 256, 0);
        coopGrid = (sms > 0 && perSM > 0) ? sms * perSM : 0;
    }

    bool ok = false;
    if (coopGrid > 0) {
        void* args[] = {(void*)&x, (void*)&y,
                        (void*)&w1, (void*)&g1, (void*)&b1, (void*)&m1, (void*)&v1,
                        (void*)&w2, (void*)&g2, (void*)&b2, (void*)&m2, (void*)&v2};
        cudaError_t err = cudaLaunchCooperativeKernel(
            (void*)se_all, dim3(coopGrid), dim3(256), args, 0, (cudaStream_t)0);
        ok = (err == cudaSuccess);
        if (!ok) (void)cudaGetLastError();   // clear and fall back
    }

    if (!ok) {
        se_reduce<<<NPLANE, 256>>>(x);
        se_excite<<<BB, 256>>>(w1, g1, b1, m1, v1, w2, g2, b2, m2, v2);
        se_scale<<<NPLANE / 2, 256>>>(x, y);
    }
}

// round 12
// speedup vs baseline: 1.8006x; 1.8006x over previous
#include <cuda_runtime.h>
#include <cstdint>

#define BB 32
#define CC 512
#define HC 128
#define HW 4096
#define NPLANE (BB * CC)
#define EPS_BN 0.001f

// scratch (no device allocations allowed anywhere)
__device__ float g_s[BB * CC];      // pooled means [B, C]
__device__ float g_es[BB * CC];     // e * scale2   [B, C]
__device__ float g_shift[CC];       // shift2       [C]

// ---------------------------------------------------------------------------
// Kernel 1: per-plane mean, full grid. Default caching -> x streams through
// L2; the tail (~126MB, highest planes) stays resident for kernel 3.
// ---------------------------------------------------------------------------
__global__ void __launch_bounds__(256) se_reduce(const float* __restrict__ x) {
    const int plane = blockIdx.x;
    const float4* xp = reinterpret_cast<const float4*>(x + (size_t)plane * HW)
                       + threadIdx.x;
    float sum = 0.f;
#pragma unroll
    for (int i = 0; i < 4; i++) {
        float4 v = xp[i * 256];
        sum += (v.x + v.y) + (v.z + v.w);
    }
#pragma unroll
    for (int o = 16; o > 0; o >>= 1)
        sum += __shfl_down_sync(0xffffffffu, sum, o);

    __shared__ float red[8];
    if ((threadIdx.x & 31) == 0) red[threadIdx.x >> 5] = sum;
    __syncthreads();
    if (threadIdx.x == 0) {
        float s = 0.f;
#pragma unroll
        for (int i = 0; i < 8; i++) s += red[i];
        g_s[plane] = s * (1.0f / HW);
    }
}

// ---------------------------------------------------------------------------
// Kernel 2: excitation MLP, one block per batch. Warp-cooperative coalesced
// dot products.
// ---------------------------------------------------------------------------
__global__ void __launch_bounds__(256) se_excite(
    const float* __restrict__ w1, const float* __restrict__ g1,
    const float* __restrict__ b1, const float* __restrict__ m1,
    const float* __restrict__ v1, const float* __restrict__ w2,
    const float* __restrict__ g2, const float* __restrict__ b2,
    const float* __restrict__ m2, const float* __restrict__ v2) {
    __shared__ float s_s[CC];
    __shared__ float s_h[HC];
    const int b = blockIdx.x, wid = threadIdx.x >> 5, lane = threadIdx.x & 31;

    for (int i = threadIdx.x; i < CC; i += 256) s_s[i] = g_s[b * CC + i];
    __syncthreads();

#pragma unroll 2
    for (int r = 0; r < 16; r++) {
        const int j = wid * 16 + r;
        const float* wr = w1 + j * CC;
        float acc = 0.f;
#pragma unroll
        for (int i = 0; i < CC / 32; i++)
            acc = fmaf(wr[lane + 32 * i], s_s[lane + 32 * i], acc);
#pragma unroll
        for (int o = 16; o > 0; o >>= 1)
            acc += __shfl_down_sync(0xffffffffu, acc, o);
        if (lane == 0) {
            float hv = (acc - m1[j]) * (g1[j] * rsqrtf(v1[j] + EPS_BN)) + b1[j];
            s_h[j] = fmaxf(hv, 0.f);
        }
    }
    __syncthreads();

#pragma unroll 2
    for (int r = 0; r < 64; r++) {
        const int c = wid * 64 + r;
        const float* wr = w2 + c * HC;
        float acc = 0.f;
#pragma unroll
        for (int i = 0; i < HC / 32; i++)
            acc = fmaf(wr[lane + 32 * i], s_h[lane + 32 * i], acc);
#pragma unroll
        for (int o = 16; o > 0; o >>= 1)
            acc += __shfl_down_sync(0xffffffffu, acc, o);
        if (lane == 0) {
            const float sc2 = g2[c] * rsqrtf(v2[c] + EPS_BN);
            g_es[b * CC + c] = acc * sc2;
            if (b == 0) g_shift[c] = fmaf(-m2[c], sc2, b2[c]);
        }
    }
}

// ---------------------------------------------------------------------------
// Kernel 3: y = x*es + shift. One plane per block, REVERSED order (first
// waves consume the L2 tail left by kernel 1). Loads via __ldcg; the result
// is staged in SMEM and written as ONE 16KB contiguous TMA bulk store —
// long DRAM write bursts instead of scattered per-warp STG.128.
// ---------------------------------------------------------------------------
__global__ void __launch_bounds__(256) se_scale(const float* __restrict__ x,
                                                float* __restrict__ y) {
    __shared__ __align__(128) float4 buf[1024];        // one 16KB plane

    const int plane = NPLANE - 1 - blockIdx.x;         // reversed
    const float es    = g_es[plane];
    const float shift = g_shift[plane & (CC - 1)];

    const size_t base = (size_t)plane * (HW / 4);
    const float4* xp = reinterpret_cast<const float4*>(x) + base + threadIdx.x;

    float4 v[4];
#pragma unroll
    for (int i = 0; i < 4; i++) v[i] = __ldcg(xp + i * 256);

#pragma unroll
    for (int i = 0; i < 4; i++) {
        float4 o;
        o.x = fmaf(v[i].x, es, shift);
        o.y = fmaf(v[i].y, es, shift);
        o.z = fmaf(v[i].z, es, shift);
        o.w = fmaf(v[i].w, es, shift);
        buf[i * 256 + threadIdx.x] = o;
    }
    __syncthreads();

    if (threadIdx.x == 0) {
        uint32_t saddr;
        asm("{ .reg .u64 t; cvta.to.shared.u64 t, %1; cvt.u32.u64 %0, t; }"
            : "=r"(saddr) : "l"(buf));
        const float4* gdst = reinterpret_cast<const float4*>(y) + base;
        asm volatile("fence.proxy.async.shared::cta;" ::: "memory");
        asm volatile(
            "cp.async.bulk.global.shared::cta.bulk_group [%0], [%1], %2;"
            :: "l"(gdst), "r"(saddr), "r"(16384) : "memory");
        asm volatile("cp.async.bulk.commit_group;" ::: "memory");
        asm volatile("cp.async.bulk.wait_group.read 0;" ::: "memory");
    }
}

// ---------------------------------------------------------------------------
extern "C" void kernel_launch(void* const* d_in, const int* in_sizes, int n_in,
                              void* d_out, int out_size) {
    const float* x  = (const float*)d_in[0];
    const float* w1 = (const float*)d_in[1];
    const float* g1 = (const float*)d_in[2];
    const float* b1 = (const float*)d_in[3];
    const float* m1 = (const float*)d_in[4];
    const float* v1 = (const float*)d_in[5];
    const float* w2 = (const float*)d_in[6];
    const float* g2 = (const float*)d_in[7];
    const float* b2 = (const float*)d_in[8];
    const float* m2 = (const float*)d_in[9];
    const float* v2 = (const float*)d_in[10];
    float* y = (float*)d_out;

    se_reduce<<<NPLANE, 256>>>(x);
    se_excite<<<BB, 256>>>(w1, g1, b1, m1, v1, w2, g2, b2, m2, v2);
    se_scale<<<NPLANE, 256>>>(x, y);
}

// round 13
// speedup vs baseline: 1.8256x; 1.0138x over previous
#include <cuda_runtime.h>

#define BB 32
#define CC 512
#define HC 128
#define HW 4096
#define NPLANE (BB * CC)
#define EPS_BN 0.001f

// scratch (no device allocations allowed anywhere)
__device__ float g_s[BB * CC];      // pooled means [B, C]
__device__ float g_es[BB * CC];     // e * scale2   [B, C]
__device__ float g_shift[CC];       // shift2       [C]

// ---------------------------------------------------------------------------
// Kernel 1: per-plane mean, full grid. Default caching -> x streams through
// L2; the tail (~126MB, highest planes) stays resident for kernel 3.
// Triggers PDL completion right after publishing its mean so the excite
// kernel can launch while this grid drains.
// ---------------------------------------------------------------------------
__global__ void __launch_bounds__(256) se_reduce(const float* __restrict__ x) {
    const int plane = blockIdx.x;
    const float4* xp = reinterpret_cast<const float4*>(x + (size_t)plane * HW)
                       + threadIdx.x;
    float sum = 0.f;
#pragma unroll
    for (int i = 0; i < 4; i++) {
        float4 v = xp[i * 256];
        sum += (v.x + v.y) + (v.z + v.w);
    }
#pragma unroll
    for (int o = 16; o > 0; o >>= 1)
        sum += __shfl_down_sync(0xffffffffu, sum, o);

    __shared__ float red[8];
    if ((threadIdx.x & 31) == 0) red[threadIdx.x >> 5] = sum;
    __syncthreads();
    if (threadIdx.x == 0) {
        float s = 0.f;
#pragma unroll
        for (int i = 0; i < 8; i++) s += red[i];
        g_s[plane] = s * (1.0f / HW);
    }
    cudaTriggerProgrammaticLaunchCompletion();
}

// ---------------------------------------------------------------------------
// Kernel 2: excitation MLP, one block per batch. Gated on reduce via PDL
// dependency sync; triggers completion after publishing g_es/g_shift.
// ---------------------------------------------------------------------------
__global__ void __launch_bounds__(256) se_excite(
    const float* __restrict__ w1, const float* __restrict__ g1,
    const float* __restrict__ b1, const float* __restrict__ m1,
    const float* __restrict__ v1, const float* __restrict__ w2,
    const float* __restrict__ g2, const float* __restrict__ b2,
    const float* __restrict__ m2, const float* __restrict__ v2) {
    __shared__ float s_s[CC];
    __shared__ float s_h[HC];
    const int b = blockIdx.x, wid = threadIdx.x >> 5, lane = threadIdx.x & 31;

    cudaGridDependencySynchronize();               // wait for all g_s writes

    for (int i = threadIdx.x; i < CC; i += 256) s_s[i] = g_s[b * CC + i];
    __syncthreads();

#pragma unroll 2
    for (int r = 0; r < 16; r++) {
        const int j = wid * 16 + r;
        const float* wr = w1 + j * CC;
        float acc = 0.f;
#pragma unroll
        for (int i = 0; i < CC / 32; i++)
            acc = fmaf(wr[lane + 32 * i], s_s[lane + 32 * i], acc);
#pragma unroll
        for (int o = 16; o > 0; o >>= 1)
            acc += __shfl_down_sync(0xffffffffu, acc, o);
        if (lane == 0) {
            float hv = (acc - m1[j]) * (g1[j] * rsqrtf(v1[j] + EPS_BN)) + b1[j];
            s_h[j] = fmaxf(hv, 0.f);
        }
    }
    __syncthreads();

#pragma unroll 2
    for (int r = 0; r < 64; r++) {
        const int c = wid * 64 + r;
        const float* wr = w2 + c * HC;
        float acc = 0.f;
#pragma unroll
        for (int i = 0; i < HC / 32; i++)
            acc = fmaf(wr[lane + 32 * i], s_h[lane + 32 * i], acc);
#pragma unroll
        for (int o = 16; o > 0; o >>= 1)
            acc += __shfl_down_sync(0xffffffffu, acc, o);
        if (lane == 0) {
            const float sc2 = g2[c] * rsqrtf(v2[c] + EPS_BN);
            g_es[b * CC + c] = acc * sc2;
            if (b == 0) g_shift[c] = fmaf(-m2[c], sc2, b2[c]);
        }
    }
    cudaTriggerProgrammaticLaunchCompletion();
}

// ---------------------------------------------------------------------------
// Kernel 3: y = x*es + shift. 2 planes per block, REVERSED order (first waves
// consume the L2 tail left by kernel 1). The 8 x-loads are issued BEFORE the
// PDL dependency sync — they don't depend on excite — so scale's DRAM reads
// overlap the excite kernel and the reduce drain.
// ---------------------------------------------------------------------------
__global__ void __launch_bounds__(256) se_scale(const float* __restrict__ x,
                                                float* __restrict__ y) {
    const int plane0 = NPLANE - 2 - blockIdx.x * 2;   // reversed

    const size_t base = (size_t)plane0 * (HW / 4);
    const float4* xp = reinterpret_cast<const float4*>(x) + base + threadIdx.x;
    float4*       yp = reinterpret_cast<float4*>(y) + base + threadIdx.x;

    // prefetch x (independent of excite) before the dependency sync
    float4 v[8];
#pragma unroll
    for (int i = 0; i < 8; i++) v[i] = __ldcg(xp + i * 256);

    cudaGridDependencySynchronize();                  // g_es / g_shift ready

    float es[2], sh[2];
#pragma unroll
    for (int p = 0; p < 2; p++) {
        es[p] = g_es[plane0 + p];
        sh[p] = g_shift[(plane0 + p) & (CC - 1)];
    }

#pragma unroll
    for (int i = 0; i < 8; i++) {
        const float e = es[i >> 2], s = sh[i >> 2];
        float4 o;
        o.x = fmaf(v[i].x, e, s);
        o.y = fmaf(v[i].y, e, s);
        o.z = fmaf(v[i].z, e, s);
        o.w = fmaf(v[i].w, e, s);
        __stcs(yp + i * 256, o);
    }
}

// ---------------------------------------------------------------------------
extern "C" void kernel_launch(void* const* d_in, const int* in_sizes, int n_in,
                              void* d_out, int out_size) {
    const float* x  = (const float*)d_in[0];
    const float* w1 = (const float*)d_in[1];
    const float* g1 = (const float*)d_in[2];
    const float* b1 = (const float*)d_in[3];
    const float* m1 = (const float*)d_in[4];
    const float* v1 = (const float*)d_in[5];
    const float* w2 = (const float*)d_in[6];
    const float* g2 = (const float*)d_in[7];
    const float* b2 = (const float*)d_in[8];
    const float* m2 = (const float*)d_in[9];
    const float* v2 = (const float*)d_in[10];
    float* y = (float*)d_out;

    // kernel 1: plain launch
    se_reduce<<<NPLANE, 256>>>(x);

    // kernels 2 & 3: programmatic dependent launches (overlap with predecessor)
    cudaLaunchAttribute attr[1];
    attr[0].id = cudaLaunchAttributeProgrammaticStreamSerialization;
    attr[0].val.programmaticStreamSerializationAllowed = 1;

    cudaLaunchConfig_t cfg2 = {};
    cfg2.gridDim  = dim3(BB);
    cfg2.blockDim = dim3(256);
    cfg2.stream   = 0;
    cfg2.attrs    = attr;
    cfg2.numAttrs = 1;
    cudaError_t e2 = cudaLaunchKernelEx(&cfg2, se_excite,
                                        w1, g1, b1, m1, v1,
                                        w2, g2, b2, m2, v2);
    if (e2 != cudaSuccess) {   // fallback: plain launch (device PDL calls are no-ops)
        (void)cudaGetLastError();
        se_excite<<<BB, 256>>>(w1, g1, b1, m1, v1, w2, g2, b2, m2, v2);
    }

    cudaLaunchConfig_t cfg3 = {};
    cfg3.gridDim  = dim3(NPLANE / 2);
    cfg3.blockDim = dim3(256);
    cfg3.stream   = 0;
    cfg3.attrs    = attr;
    cfg3.numAttrs = 1;
    cudaError_t e3 = cudaLaunchKernelEx(&cfg3, se_scale, x, y);
    if (e3 != cudaSuccess) {
        (void)cudaGetLastError();
        se_scale<<<NPLANE / 2, 256>>>(x, y);
    }
}